// round 1
// baseline (speedup 1.0000x reference)
#include <cuda_runtime.h>
#include <math.h>

#define BB 16384
#define SS 16
#define NSTEPS 50
#define LATENT 128
#define HID 64
#define DTC 0.02f
#define SQRT_DT 0.14142135623730951f
#define TEMPC 20.0f
#define K2LOG2E 2.8853900817779268f   /* 2*log2(e) */
#define LOG2E 1.4426950408889634f
#define LN2 0.6931471805599453f
#define EXPM50 1.9287498479639178e-22f /* exp(-50) */

// Scratch (no cudaMalloc allowed)
__device__ float g_zc[BB * HID];   // per-b hidden bias: z@W1[:,2:].T + b1
__device__ float g_halfb[BB];      // 0.5*boundary
__device__ float g_ndt[BB];        // non-decision time

__device__ __forceinline__ float ex2f(float v) {
    float r; asm("ex2.approx.f32 %0, %1;" : "=f"(r) : "f"(v)); return r;
}
__device__ __forceinline__ float rcpf(float v) {
    float r; asm("rcp.approx.f32 %0, %1;" : "=f"(r) : "f"(v)); return r;
}
__device__ __forceinline__ float lg2f(float v) {
    float r; asm("lg2.approx.f32 %0, %1;" : "=f"(r) : "f"(v)); return r;
}
__device__ __forceinline__ float fix_out(float v) {
    if (isnan(v)) return 0.0f;
    return fminf(fmaxf(v, -3.402823466e38f), 3.402823466e38f);
}

// ---------------------------------------------------------------------------
// Precompute: zc[b][j] = b1[j] + sum_k z[b,k]*W1[j,2+k]; boundary & ndt per b.
// Block: 256 threads = (bg 0..3) x (j 0..63); each block handles 16 b's.
// ---------------------------------------------------------------------------
__global__ __launch_bounds__(256) void precompute_kernel(
    const float* __restrict__ z,  const float* __restrict__ W1,
    const float* __restrict__ b1, const float* __restrict__ Wb,
    const float* __restrict__ bbv, const float* __restrict__ Wn,
    const float* __restrict__ bnv)
{
    __shared__ __align__(16) float sW[HID * 130];   // whole W1, 33.3KB
    __shared__ __align__(16) float sz[16 * LATENT]; // 16 z rows, 8KB
    const int tid = threadIdx.x;
    const int b0 = blockIdx.x * 16;

    for (int i = tid; i < HID * 130; i += 256) sW[i] = W1[i];
    for (int i = tid; i < 16 * LATENT; i += 256) sz[i] = z[b0 * LATENT + i];
    __syncthreads();

    const int j = tid & 63;
    const int bg = tid >> 6;   // 0..3, each handles 4 b's
    const float* wrow = sW + j * 130 + 2;
    float a0, a1, a2, a3;
    a0 = a1 = a2 = a3 = b1[j];
    const float* z0 = sz + (bg * 4 + 0) * LATENT;
    const float* z1 = sz + (bg * 4 + 1) * LATENT;
    const float* z2 = sz + (bg * 4 + 2) * LATENT;
    const float* z3 = sz + (bg * 4 + 3) * LATENT;
    #pragma unroll 8
    for (int k = 0; k < LATENT; k += 4) {
        float w0 = wrow[k], w1 = wrow[k + 1], w2 = wrow[k + 2], w3 = wrow[k + 3];
        float4 q0 = *(const float4*)(z0 + k);
        float4 q1 = *(const float4*)(z1 + k);
        float4 q2 = *(const float4*)(z2 + k);
        float4 q3 = *(const float4*)(z3 + k);
        a0 = fmaf(w0, q0.x, a0); a0 = fmaf(w1, q0.y, a0); a0 = fmaf(w2, q0.z, a0); a0 = fmaf(w3, q0.w, a0);
        a1 = fmaf(w0, q1.x, a1); a1 = fmaf(w1, q1.y, a1); a1 = fmaf(w2, q1.z, a1); a1 = fmaf(w3, q1.w, a1);
        a2 = fmaf(w0, q2.x, a2); a2 = fmaf(w1, q2.y, a2); a2 = fmaf(w2, q2.z, a2); a2 = fmaf(w3, q2.w, a2);
        a3 = fmaf(w0, q3.x, a3); a3 = fmaf(w1, q3.y, a3); a3 = fmaf(w2, q3.z, a3); a3 = fmaf(w3, q3.w, a3);
    }
    g_zc[(b0 + bg * 4 + 0) * HID + j] = a0;
    g_zc[(b0 + bg * 4 + 1) * HID + j] = a1;
    g_zc[(b0 + bg * 4 + 2) * HID + j] = a2;
    g_zc[(b0 + bg * 4 + 3) * HID + j] = a3;

    // boundary/ndt: 32 threads, each a full 128-dot (cheap)
    if (tid < 32) {
        const int bl = tid >> 1;
        const int isn = tid & 1;
        const float* wv = isn ? Wn : Wb;
        const float* zz = sz + bl * LATENT;
        float acc = isn ? bnv[0] : bbv[0];
        #pragma unroll 8
        for (int k = 0; k < LATENT; k++) acc = fmaf(wv[k], zz[k], acc);
        float sp = fmaxf(acc, 0.0f) + log1pf(expf(-fabsf(acc)));
        if (isn) g_ndt[b0 + bl] = sp + 0.05f;
        else     g_halfb[b0 + bl] = 0.5f * (sp + 0.3f);
    }
}

// ---------------------------------------------------------------------------
// Main SDE kernel. 4 lanes per (b,s); lane owns 16 of 64 hidden units, all
// weights in registers. Block of 256 = 4 b's x 16 sims x 4 reps.
// ---------------------------------------------------------------------------
__global__ __launch_bounds__(256, 2) void sde_kernel(
    const float* __restrict__ W1, const float* __restrict__ W2,
    const float* __restrict__ b2, const float* __restrict__ noise,
    const float* __restrict__ osc, const float* __restrict__ obi,
    float* __restrict__ out)
{
    const int tid = threadIdx.x;
    const int rep = tid & 3;          // which 16-unit slice
    const int s   = (tid >> 2) & 15;  // sim
    const int bl  = tid >> 6;         // 0..3
    const int b   = blockIdx.x * 4 + bl;
    const int jbase = rep * 16;

    float w1xK[16], w1tK[16], zcK[16], w2a[16], w2b[16];
    float sumA = 0.0f, sumB = 0.0f;
    #pragma unroll
    for (int i = 0; i < 16; i++) {
        const int j = jbase + i;
        w1xK[i] = W1[j * 130 + 0] * K2LOG2E;
        w1tK[i] = W1[j * 130 + 1] * K2LOG2E;
        zcK[i]  = g_zc[b * HID + j] * K2LOG2E;
        w2a[i]  = W2[j];
        w2b[i]  = W2[HID + j];
        sumA += w2a[i];
        sumB += w2b[i];
    }
    const float b2x = b2[0], b2y = b2[1];
    const float half_b = g_halfb[b];

    float x = 0.0f, p = 1.0f, exp_rt = 0.0f, exp_corr = 0.0f;
    const int nidx = b * SS + s;
    float nz = noise[nidx];

    #pragma unroll 1
    for (int k = 0; k < NSTEPS; k++) {
        const int k1 = (k + 1 < NSTEPS) ? (k + 1) : (NSTEPS - 1);
        const float nz_next = noise[k1 * (BB * SS) + nidx];  // prefetch
        const float tk = (float)k * DTC;

        float da = 0.0f, db = 0.0f;
        #pragma unroll
        for (int i = 0; i < 16; i++) {
            // u = 2*log2e * (x*w1x + t*w1t + zc) ; tanh(a) = 1 - 2/(1+2^u)
            float u = fmaf(x, w1xK[i], fmaf(tk, w1tK[i], zcK[i]));
            float e = ex2f(u);
            float r = rcpf(e + 1.0f);
            da = fmaf(r, w2a[i], da);
            db = fmaf(r, w2b[i], db);
        }
        // sum h*w2 = sum w2 - 2*sum r*w2
        float pd = fmaf(-2.0f, da, sumA);
        float pf = fmaf(-2.0f, db, sumB);
        pd += __shfl_xor_sync(0xffffffffu, pd, 1);
        pf += __shfl_xor_sync(0xffffffffu, pf, 1);
        pd += __shfl_xor_sync(0xffffffffu, pd, 2);
        pf += __shfl_xor_sync(0xffffffffu, pf, 2);

        const float dyn0 = pd + b2x;
        const float dyn1 = pf + b2y;
        const float drift = fminf(fmaxf(dyn0, -5.0f), 5.0f);
        // softplus(dyn1) = max(v,0) + ln(1 + e^{-|v|})
        const float e1 = ex2f(-fabsf(dyn1) * LOG2E);
        const float sp = fmaxf(dyn1, 0.0f) + lg2f(1.0f + e1) * LN2;
        const float diff = sp + 0.1f;

        x = fmaf(diff * SQRT_DT, nz, fmaf(drift, DTC, x));
        x = fminf(fmaxf(x, -10.0f), 10.0f);

        const float dist = fabsf(x) - half_b;
        const float eh = ex2f(dist * (-TEMPC * LOG2E)); // e^{-20*dist}
        const float sig = rcpf(1.0f + eh);              // sigmoid(20*dist)
        const float hz = fminf(fmaxf(sig, 0.0f), 0.99f);
        const float sb = fmaxf(p, EXPM50);              // exp(max(log_surv,-50))
        const float cp = sb * hz;
        p = p * (1.0f - hz);
        exp_rt = fmaf(cp, (float)(k + 1) * DTC, exp_rt);
        if (x > 0.0f) exp_corr += cp;

        nz = nz_next;
    }

    const float rem = fmaxf(p, EXPM50);
    exp_rt  = fmaf(rem, (float)NSTEPS * DTC, exp_rt);  // + rem * 1.0
    exp_corr = fmaf(rem, 0.5f, exp_corr);
    const float rt_ms = (exp_rt + g_ndt[b]) * 1000.0f;

    // per-b reduction over the 16 sims (each sim duplicated on 4 lanes;
    // rep==0 lanes publish)
    __shared__ float s_rt[4][16];
    __shared__ float s_cr[4][16];
    if (rep == 0) { s_rt[bl][s] = rt_ms; s_cr[bl][s] = exp_corr; }
    __syncthreads();

    if (tid < 4) {
        float m = 0.0f, c = 0.0f;
        #pragma unroll
        for (int i = 0; i < 16; i++) { m += s_rt[tid][i]; c += s_cr[tid][i]; }
        m *= (1.0f / 16.0f);
        c *= (1.0f / 16.0f);
        float v = 0.0f;
        #pragma unroll
        for (int i = 0; i < 16; i++) {
            float d = s_rt[tid][i] - m;
            v = fmaf(d, d, v);
        }
        const float sd = sqrtf(v * (1.0f / 15.0f));  // ddof=1
        const int bo = blockIdx.x * 4 + tid;
        const float o0 = m * osc[0] + obi[0];
        const float o1 = (sd + 0.001f) * osc[1] + obi[1];
        const float o2 = c * osc[2] + obi[2];
        out[bo * 3 + 0] = fix_out(o0);
        out[bo * 3 + 1] = fix_out(o1);
        out[bo * 3 + 2] = fix_out(o2);
    }
}

extern "C" void kernel_launch(void* const* d_in, const int* in_sizes, int n_in,
                              void* d_out, int out_size)
{
    const float* z   = (const float*)d_in[0];
    const float* W1  = (const float*)d_in[1];
    const float* b1  = (const float*)d_in[2];
    const float* W2  = (const float*)d_in[3];
    const float* b2  = (const float*)d_in[4];
    const float* Wb  = (const float*)d_in[5];
    const float* bbv = (const float*)d_in[6];
    const float* Wn  = (const float*)d_in[7];
    const float* bnv = (const float*)d_in[8];
    const float* osc = (const float*)d_in[9];
    const float* obi = (const float*)d_in[10];
    const float* noise = (const float*)d_in[11];
    float* out = (float*)d_out;

    precompute_kernel<<<BB / 16, 256>>>(z, W1, b1, Wb, bbv, Wn, bnv);
    sde_kernel<<<BB / 4, 256>>>(W1, W2, b2, noise, osc, obi, out);
}

// round 2
// speedup vs baseline: 1.4068x; 1.4068x over previous
#include <cuda_runtime.h>
#include <math.h>

#define BB 16384
#define SS 16
#define NSTEPS 50
#define LATENT 128
#define HID 64
#define DTC 0.02f
#define SQRT_DT 0.14142135623730951f
#define TEMPC 20.0f
#define K2LOG2E 2.8853900817779268f   /* 2*log2(e) */
#define LOG2E 1.4426950408889634f
#define LN2 0.6931471805599453f
#define EXPM50 1.9287498479639178e-22f /* exp(-50) */

// Scratch (no cudaMalloc allowed)
__device__ float g_zc[BB * HID];   // per-b hidden bias: z@W1[:,2:].T + b1
__device__ float g_halfb[BB];      // 0.5*boundary
__device__ float g_ndt[BB];        // non-decision time

__device__ __forceinline__ float ex2f(float v) {
    float r; asm("ex2.approx.f32 %0, %1;" : "=f"(r) : "f"(v)); return r;
}
__device__ __forceinline__ float rcpf(float v) {
    float r; asm("rcp.approx.f32 %0, %1;" : "=f"(r) : "f"(v)); return r;
}
__device__ __forceinline__ float lg2f(float v) {
    float r; asm("lg2.approx.f32 %0, %1;" : "=f"(r) : "f"(v)); return r;
}
__device__ __forceinline__ float fix_out(float v) {
    if (isnan(v)) return 0.0f;
    return fminf(fmaxf(v, -3.402823466e38f), 3.402823466e38f);
}

// ---------------------------------------------------------------------------
// Precompute: zc[b][j] = b1[j] + sum_k z[b,k]*W1[j,2+k]; boundary & ndt per b.
// ---------------------------------------------------------------------------
__global__ __launch_bounds__(256) void precompute_kernel(
    const float* __restrict__ z,  const float* __restrict__ W1,
    const float* __restrict__ b1, const float* __restrict__ Wb,
    const float* __restrict__ bbv, const float* __restrict__ Wn,
    const float* __restrict__ bnv)
{
    __shared__ __align__(16) float sW[HID * 130];   // whole W1, 33.3KB
    __shared__ __align__(16) float sz[16 * LATENT]; // 16 z rows, 8KB
    const int tid = threadIdx.x;
    const int b0 = blockIdx.x * 16;

    for (int i = tid; i < HID * 130; i += 256) sW[i] = W1[i];
    for (int i = tid; i < 16 * LATENT; i += 256) sz[i] = z[b0 * LATENT + i];
    __syncthreads();

    const int j = tid & 63;
    const int bg = tid >> 6;   // 0..3, each handles 4 b's
    const float* wrow = sW + j * 130 + 2;
    float a0, a1, a2, a3;
    a0 = a1 = a2 = a3 = b1[j];
    const float* z0 = sz + (bg * 4 + 0) * LATENT;
    const float* z1 = sz + (bg * 4 + 1) * LATENT;
    const float* z2 = sz + (bg * 4 + 2) * LATENT;
    const float* z3 = sz + (bg * 4 + 3) * LATENT;
    #pragma unroll 8
    for (int k = 0; k < LATENT; k += 4) {
        float w0 = wrow[k], w1 = wrow[k + 1], w2 = wrow[k + 2], w3 = wrow[k + 3];
        float4 q0 = *(const float4*)(z0 + k);
        float4 q1 = *(const float4*)(z1 + k);
        float4 q2 = *(const float4*)(z2 + k);
        float4 q3 = *(const float4*)(z3 + k);
        a0 = fmaf(w0, q0.x, a0); a0 = fmaf(w1, q0.y, a0); a0 = fmaf(w2, q0.z, a0); a0 = fmaf(w3, q0.w, a0);
        a1 = fmaf(w0, q1.x, a1); a1 = fmaf(w1, q1.y, a1); a1 = fmaf(w2, q1.z, a1); a1 = fmaf(w3, q1.w, a1);
        a2 = fmaf(w0, q2.x, a2); a2 = fmaf(w1, q2.y, a2); a2 = fmaf(w2, q2.z, a2); a2 = fmaf(w3, q2.w, a2);
        a3 = fmaf(w0, q3.x, a3); a3 = fmaf(w1, q3.y, a3); a3 = fmaf(w2, q3.z, a3); a3 = fmaf(w3, q3.w, a3);
    }
    g_zc[(b0 + bg * 4 + 0) * HID + j] = a0;
    g_zc[(b0 + bg * 4 + 1) * HID + j] = a1;
    g_zc[(b0 + bg * 4 + 2) * HID + j] = a2;
    g_zc[(b0 + bg * 4 + 3) * HID + j] = a3;

    if (tid < 32) {
        const int bl = tid >> 1;
        const int isn = tid & 1;
        const float* wv = isn ? Wn : Wb;
        const float* zz = sz + bl * LATENT;
        float acc = isn ? bnv[0] : bbv[0];
        #pragma unroll 8
        for (int k = 0; k < LATENT; k++) acc = fmaf(wv[k], zz[k], acc);
        float sp = fmaxf(acc, 0.0f) + log1pf(expf(-fabsf(acc)));
        if (isn) g_ndt[b0 + bl] = sp + 0.05f;
        else     g_halfb[b0 + bl] = 0.5f * (sp + 0.3f);
    }
}

// ---------------------------------------------------------------------------
// Main SDE kernel. 8 lanes per (b,s); each lane owns 8 of 64 hidden units.
// Weight regs: 5*8 = 40 -> no spills, ~3 blocks/SM.
// Block of 256 = 2 b's x 16 sims x 8 reps.
// ---------------------------------------------------------------------------
__global__ __launch_bounds__(256, 3) void sde_kernel(
    const float* __restrict__ W1, const float* __restrict__ W2,
    const float* __restrict__ b2, const float* __restrict__ noise,
    const float* __restrict__ osc, const float* __restrict__ obi,
    float* __restrict__ out)
{
    const int tid = threadIdx.x;
    const int rep = tid & 7;          // which 8-unit slice
    const int s   = (tid >> 3) & 15;  // sim
    const int bl  = tid >> 7;         // 0..1
    const int b   = blockIdx.x * 2 + bl;
    const int jbase = rep * 8;

    float w1xK[8], w1tK[8], zcK[8], w2a[8], w2b[8];
    float sumA = 0.0f, sumB = 0.0f;
    #pragma unroll
    for (int i = 0; i < 8; i++) {
        const int j = jbase + i;
        w1xK[i] = W1[j * 130 + 0] * K2LOG2E;
        w1tK[i] = W1[j * 130 + 1] * K2LOG2E;
        zcK[i]  = g_zc[b * HID + j] * K2LOG2E;
        w2a[i]  = W2[j];
        w2b[i]  = W2[HID + j];
        sumA += w2a[i];
        sumB += w2b[i];
    }
    const float b2x = b2[0], b2y = b2[1];
    const float half_b = g_halfb[b];

    float x = 0.0f, p = 1.0f, exp_rt = 0.0f, exp_corr = 0.0f;
    const int nidx = b * SS + s;
    float nz = noise[nidx];

    #pragma unroll 1
    for (int k = 0; k < NSTEPS; k++) {
        const int k1 = (k + 1 < NSTEPS) ? (k + 1) : (NSTEPS - 1);
        const float nz_next = noise[k1 * (BB * SS) + nidx];  // prefetch
        const float tk = (float)k * DTC;

        float da = 0.0f, db = 0.0f;
        #pragma unroll
        for (int i = 0; i < 8; i++) {
            // u = 2*log2e * (x*w1x + t*w1t + zc) ; tanh(a) = 1 - 2/(1+2^u)
            float u = fmaf(x, w1xK[i], fmaf(tk, w1tK[i], zcK[i]));
            float e = ex2f(u);
            float r = rcpf(e + 1.0f);
            da = fmaf(r, w2a[i], da);
            db = fmaf(r, w2b[i], db);
        }
        // sum h*w2 = sum w2 - 2*sum r*w2
        float pd = fmaf(-2.0f, da, sumA);
        float pf = fmaf(-2.0f, db, sumB);
        pd += __shfl_xor_sync(0xffffffffu, pd, 1);
        pf += __shfl_xor_sync(0xffffffffu, pf, 1);
        pd += __shfl_xor_sync(0xffffffffu, pd, 2);
        pf += __shfl_xor_sync(0xffffffffu, pf, 2);
        pd += __shfl_xor_sync(0xffffffffu, pd, 4);
        pf += __shfl_xor_sync(0xffffffffu, pf, 4);

        const float dyn0 = pd + b2x;
        const float dyn1 = pf + b2y;
        const float drift = fminf(fmaxf(dyn0, -5.0f), 5.0f);
        // softplus(dyn1) = max(v,0) + ln(1 + e^{-|v|})
        const float e1 = ex2f(-fabsf(dyn1) * LOG2E);
        const float sp = fmaxf(dyn1, 0.0f) + lg2f(1.0f + e1) * LN2;
        const float diff = sp + 0.1f;

        x = fmaf(diff * SQRT_DT, nz, fmaf(drift, DTC, x));
        x = fminf(fmaxf(x, -10.0f), 10.0f);

        const float dist = fabsf(x) - half_b;
        const float eh = ex2f(dist * (-TEMPC * LOG2E)); // e^{-20*dist}
        const float sig = rcpf(1.0f + eh);              // sigmoid(20*dist)
        const float hz = fminf(fmaxf(sig, 0.0f), 0.99f);
        const float sb = fmaxf(p, EXPM50);              // exp(max(log_surv,-50))
        const float cp = sb * hz;
        p = p * (1.0f - hz);
        exp_rt = fmaf(cp, (float)(k + 1) * DTC, exp_rt);
        exp_corr += (x > 0.0f) ? cp : 0.0f;

        nz = nz_next;
    }

    const float rem = fmaxf(p, EXPM50);
    exp_rt  = fmaf(rem, (float)NSTEPS * DTC, exp_rt);  // + rem * 1.0
    exp_corr = fmaf(rem, 0.5f, exp_corr);
    const float rt_ms = (exp_rt + g_ndt[b]) * 1000.0f;

    // per-b reduction over the 16 sims (each sim duplicated on 8 lanes;
    // rep==0 lanes publish)
    __shared__ float s_rt[2][16];
    __shared__ float s_cr[2][16];
    if (rep == 0) { s_rt[bl][s] = rt_ms; s_cr[bl][s] = exp_corr; }
    __syncthreads();

    if (tid < 2) {
        float m = 0.0f, c = 0.0f;
        #pragma unroll
        for (int i = 0; i < 16; i++) { m += s_rt[tid][i]; c += s_cr[tid][i]; }
        m *= (1.0f / 16.0f);
        c *= (1.0f / 16.0f);
        float v = 0.0f;
        #pragma unroll
        for (int i = 0; i < 16; i++) {
            float d = s_rt[tid][i] - m;
            v = fmaf(d, d, v);
        }
        const float sd = sqrtf(v * (1.0f / 15.0f));  // ddof=1
        const int bo = blockIdx.x * 2 + tid;
        const float o0 = m * osc[0] + obi[0];
        const float o1 = (sd + 0.001f) * osc[1] + obi[1];
        const float o2 = c * osc[2] + obi[2];
        out[bo * 3 + 0] = fix_out(o0);
        out[bo * 3 + 1] = fix_out(o1);
        out[bo * 3 + 2] = fix_out(o2);
    }
}

extern "C" void kernel_launch(void* const* d_in, const int* in_sizes, int n_in,
                              void* d_out, int out_size)
{
    const float* z   = (const float*)d_in[0];
    const float* W1  = (const float*)d_in[1];
    const float* b1  = (const float*)d_in[2];
    const float* W2  = (const float*)d_in[3];
    const float* b2  = (const float*)d_in[4];
    const float* Wb  = (const float*)d_in[5];
    const float* bbv = (const float*)d_in[6];
    const float* Wn  = (const float*)d_in[7];
    const float* bnv = (const float*)d_in[8];
    const float* osc = (const float*)d_in[9];
    const float* obi = (const float*)d_in[10];
    const float* noise = (const float*)d_in[11];
    float* out = (float*)d_out;

    precompute_kernel<<<BB / 16, 256>>>(z, W1, b1, Wb, bbv, Wn, bnv);
    sde_kernel<<<BB / 2, 256>>>(W1, W2, b2, noise, osc, obi, out);
}

// round 3
// speedup vs baseline: 2.7913x; 1.9842x over previous
#include <cuda_runtime.h>
#include <math.h>

#define BB 16384
#define SS 16
#define NSTEPS 50
#define LATENT 128
#define HID 64
#define DTC 0.02f
#define SQRT_DT 0.14142135623730951f
#define LOG2E 1.4426950408889634f
#define LN2 0.6931471805599453f
#define EXPM50 1.9287498479639178e-22f /* exp(-50) */

typedef unsigned long long u64t;

// Scratch (no cudaMalloc allowed)
__device__ float g_zc[BB * HID];   // per-b hidden bias: z@W1[:,2:].T + b1
__device__ float g_halfb[BB];      // 0.5*boundary
__device__ float g_ndt[BB];        // non-decision time

__device__ __forceinline__ float ex2f(float v) {
    float r; asm("ex2.approx.f32 %0, %1;" : "=f"(r) : "f"(v)); return r;
}
__device__ __forceinline__ float lg2f(float v) {
    float r; asm("lg2.approx.f32 %0, %1;" : "=f"(r) : "f"(v)); return r;
}
__device__ __forceinline__ float tanhapx(float v) {
    float r; asm("tanh.approx.f32 %0, %1;" : "=f"(r) : "f"(v)); return r;
}
__device__ __forceinline__ u64t pack2(float lo, float hi) {
    u64t r;
    asm("mov.b64 %0, {%1, %2};" : "=l"(r)
        : "r"(__float_as_uint(lo)), "r"(__float_as_uint(hi)));
    return r;
}
__device__ __forceinline__ void unpack2(u64t v, float& lo, float& hi) {
    unsigned a, b;
    asm("mov.b64 {%0, %1}, %2;" : "=r"(a), "=r"(b) : "l"(v));
    lo = __uint_as_float(a); hi = __uint_as_float(b);
}
__device__ __forceinline__ u64t fma2(u64t a, u64t b, u64t c) {
    u64t r; asm("fma.rn.f32x2 %0, %1, %2, %3;" : "=l"(r) : "l"(a), "l"(b), "l"(c));
    return r;
}
__device__ __forceinline__ float fix_out(float v) {
    if (isnan(v)) return 0.0f;
    return fminf(fmaxf(v, -3.402823466e38f), 3.402823466e38f);
}

// ---------------------------------------------------------------------------
// Precompute: zc[b][j] = b1[j] + sum_k z[b,k]*W1[j,2+k]; boundary & ndt per b.
// ---------------------------------------------------------------------------
__global__ __launch_bounds__(256) void precompute_kernel(
    const float* __restrict__ z,  const float* __restrict__ W1,
    const float* __restrict__ b1, const float* __restrict__ Wb,
    const float* __restrict__ bbv, const float* __restrict__ Wn,
    const float* __restrict__ bnv)
{
    __shared__ __align__(16) float sW[HID * 130];   // whole W1, 33.3KB
    __shared__ __align__(16) float sz[16 * LATENT]; // 16 z rows, 8KB
    const int tid = threadIdx.x;
    const int b0 = blockIdx.x * 16;

    for (int i = tid; i < HID * 130; i += 256) sW[i] = W1[i];
    for (int i = tid; i < 16 * LATENT; i += 256) sz[i] = z[b0 * LATENT + i];
    __syncthreads();

    const int j = tid & 63;
    const int bg = tid >> 6;   // 0..3, each handles 4 b's
    const float* wrow = sW + j * 130 + 2;
    float a0, a1, a2, a3;
    a0 = a1 = a2 = a3 = b1[j];
    const float* z0 = sz + (bg * 4 + 0) * LATENT;
    const float* z1 = sz + (bg * 4 + 1) * LATENT;
    const float* z2 = sz + (bg * 4 + 2) * LATENT;
    const float* z3 = sz + (bg * 4 + 3) * LATENT;
    #pragma unroll 8
    for (int k = 0; k < LATENT; k += 4) {
        float w0 = wrow[k], w1 = wrow[k + 1], w2 = wrow[k + 2], w3 = wrow[k + 3];
        float4 q0 = *(const float4*)(z0 + k);
        float4 q1 = *(const float4*)(z1 + k);
        float4 q2 = *(const float4*)(z2 + k);
        float4 q3 = *(const float4*)(z3 + k);
        a0 = fmaf(w0, q0.x, a0); a0 = fmaf(w1, q0.y, a0); a0 = fmaf(w2, q0.z, a0); a0 = fmaf(w3, q0.w, a0);
        a1 = fmaf(w0, q1.x, a1); a1 = fmaf(w1, q1.y, a1); a1 = fmaf(w2, q1.z, a1); a1 = fmaf(w3, q1.w, a1);
        a2 = fmaf(w0, q2.x, a2); a2 = fmaf(w1, q2.y, a2); a2 = fmaf(w2, q2.z, a2); a2 = fmaf(w3, q2.w, a2);
        a3 = fmaf(w0, q3.x, a3); a3 = fmaf(w1, q3.y, a3); a3 = fmaf(w2, q3.z, a3); a3 = fmaf(w3, q3.w, a3);
    }
    g_zc[(b0 + bg * 4 + 0) * HID + j] = a0;
    g_zc[(b0 + bg * 4 + 1) * HID + j] = a1;
    g_zc[(b0 + bg * 4 + 2) * HID + j] = a2;
    g_zc[(b0 + bg * 4 + 3) * HID + j] = a3;

    if (tid < 32) {
        const int bl = tid >> 1;
        const int isn = tid & 1;
        const float* wv = isn ? Wn : Wb;
        const float* zz = sz + bl * LATENT;
        float acc = isn ? bnv[0] : bbv[0];
        #pragma unroll 8
        for (int k = 0; k < LATENT; k++) acc = fmaf(wv[k], zz[k], acc);
        float sp = fmaxf(acc, 0.0f) + log1pf(expf(-fabsf(acc)));
        if (isn) g_ndt[b0 + bl] = sp + 0.05f;
        else     g_halfb[b0 + bl] = 0.5f * (sp + 0.3f);
    }
}

// ---------------------------------------------------------------------------
// Main SDE kernel. 4 lanes per (b,s); each lane owns 16 of 64 hidden units,
// stored as 8 f32x2 pairs. tanh via MUFU.TANH (1 MUFU/unit). Inner FMAs use
// fma.rn.f32x2. Block of 128 = 2 b's x 16 sims x 4 reps.
// ---------------------------------------------------------------------------
__global__ __launch_bounds__(128, 4) void sde_kernel(
    const float* __restrict__ W1, const float* __restrict__ W2,
    const float* __restrict__ b2, const float* __restrict__ noise,
    const float* __restrict__ osc, const float* __restrict__ obi,
    float* __restrict__ out)
{
    const int tid = threadIdx.x;
    const int rep = tid & 3;          // which 16-unit slice
    const int s   = (tid >> 2) & 15;  // sim
    const int bl  = tid >> 6;         // 0..1
    const int b   = blockIdx.x * 2 + bl;
    const int jbase = rep * 16;

    u64t w1x2[8], w1t2[8], zc2[8], w2a2[8], w2b2[8];
    #pragma unroll
    for (int p = 0; p < 8; p++) {
        const int j = jbase + p * 2;
        w1x2[p] = pack2(W1[j * 130],       W1[(j + 1) * 130]);
        w1t2[p] = pack2(W1[j * 130 + 1],   W1[(j + 1) * 130 + 1]);
        zc2[p]  = pack2(g_zc[b * HID + j], g_zc[b * HID + j + 1]);
        w2a2[p] = pack2(W2[j],             W2[j + 1]);
        w2b2[p] = pack2(W2[HID + j],       W2[HID + j + 1]);
    }
    const float b2x = b2[0], b2y = b2[1];
    const float half_b = g_halfb[b];

    float x = 0.0f, p_surv = 1.0f, exp_rt = 0.0f, exp_corr = 0.0f;
    const int nidx = b * SS + s;
    float nz = noise[nidx];

    #pragma unroll 1
    for (int k = 0; k < NSTEPS; k++) {
        const int k1 = (k + 1 < NSTEPS) ? (k + 1) : (NSTEPS - 1);
        const float nz_next = noise[k1 * (BB * SS) + nidx];  // prefetch
        const float tk = (float)k * DTC;
        const u64t tk2 = pack2(tk, tk);
        const u64t x2  = pack2(x, x);

        u64t da2 = 0ull, db2 = 0ull;
        #pragma unroll
        for (int p = 0; p < 8; p++) {
            u64t u2 = fma2(tk2, w1t2[p], zc2[p]);
            u2 = fma2(x2, w1x2[p], u2);
            float ulo, uhi; unpack2(u2, ulo, uhi);
            const u64t h2 = pack2(tanhapx(ulo), tanhapx(uhi));
            da2 = fma2(h2, w2a2[p], da2);
            db2 = fma2(h2, w2b2[p], db2);
        }
        float dal, dah, dbl, dbh;
        unpack2(da2, dal, dah);
        unpack2(db2, dbl, dbh);
        float pd = dal + dah;
        float pf = dbl + dbh;
        pd += __shfl_xor_sync(0xffffffffu, pd, 1);
        pf += __shfl_xor_sync(0xffffffffu, pf, 1);
        pd += __shfl_xor_sync(0xffffffffu, pd, 2);
        pf += __shfl_xor_sync(0xffffffffu, pf, 2);

        const float dyn0 = pd + b2x;
        const float dyn1 = pf + b2y;
        const float drift = fminf(fmaxf(dyn0, -5.0f), 5.0f);
        // softplus(dyn1) = max(v,0) + ln(1 + e^{-|v|})
        const float e1 = ex2f(-fabsf(dyn1) * LOG2E);
        const float sp = fmaxf(dyn1, 0.0f) + lg2f(1.0f + e1) * LN2;
        const float diff = sp + 0.1f;

        x = fmaf(diff * SQRT_DT, nz, fmaf(drift, DTC, x));
        x = fminf(fmaxf(x, -10.0f), 10.0f);

        const float dist = fabsf(x) - half_b;
        // sigmoid(20*dist) = 0.5 + 0.5*tanh(10*dist)
        const float sg = fmaf(0.5f, tanhapx(10.0f * dist), 0.5f);
        const float hz = fminf(fmaxf(sg, 0.0f), 0.99f);
        const float sb = fmaxf(p_surv, EXPM50);
        const float cp = sb * hz;
        p_surv = p_surv * (1.0f - hz);
        exp_rt = fmaf(cp, tk + DTC, exp_rt);
        exp_corr += (x > 0.0f) ? cp : 0.0f;

        nz = nz_next;
    }

    const float rem = fmaxf(p_surv, EXPM50);
    exp_rt  = fmaf(rem, (float)NSTEPS * DTC, exp_rt);
    exp_corr = fmaf(rem, 0.5f, exp_corr);
    const float rt_ms = (exp_rt + g_ndt[b]) * 1000.0f;

    // per-b reduction over the 16 sims
    __shared__ float s_rt[2][16];
    __shared__ float s_cr[2][16];
    if (rep == 0) { s_rt[bl][s] = rt_ms; s_cr[bl][s] = exp_corr; }
    __syncthreads();

    if (tid < 2) {
        float m = 0.0f, c = 0.0f;
        #pragma unroll
        for (int i = 0; i < 16; i++) { m += s_rt[tid][i]; c += s_cr[tid][i]; }
        m *= (1.0f / 16.0f);
        c *= (1.0f / 16.0f);
        float v = 0.0f;
        #pragma unroll
        for (int i = 0; i < 16; i++) {
            float d = s_rt[tid][i] - m;
            v = fmaf(d, d, v);
        }
        const float sd = sqrtf(v * (1.0f / 15.0f));  // ddof=1
        const int bo = blockIdx.x * 2 + tid;
        const float o0 = m * osc[0] + obi[0];
        const float o1 = (sd + 0.001f) * osc[1] + obi[1];
        const float o2 = c * osc[2] + obi[2];
        out[bo * 3 + 0] = fix_out(o0);
        out[bo * 3 + 1] = fix_out(o1);
        out[bo * 3 + 2] = fix_out(o2);
    }
}

extern "C" void kernel_launch(void* const* d_in, const int* in_sizes, int n_in,
                              void* d_out, int out_size)
{
    const float* z   = (const float*)d_in[0];
    const float* W1  = (const float*)d_in[1];
    const float* b1  = (const float*)d_in[2];
    const float* W2  = (const float*)d_in[3];
    const float* b2  = (const float*)d_in[4];
    const float* Wb  = (const float*)d_in[5];
    const float* bbv = (const float*)d_in[6];
    const float* Wn  = (const float*)d_in[7];
    const float* bnv = (const float*)d_in[8];
    const float* osc = (const float*)d_in[9];
    const float* obi = (const float*)d_in[10];
    const float* noise = (const float*)d_in[11];
    float* out = (float*)d_out;

    precompute_kernel<<<BB / 16, 256>>>(z, W1, b1, Wb, bbv, Wn, bnv);
    sde_kernel<<<BB / 2, 128>>>(W1, W2, b2, noise, osc, obi, out);
}

// round 4
// speedup vs baseline: 2.8494x; 1.0208x over previous
#include <cuda_runtime.h>
#include <math.h>

#define BB 16384
#define SS 16
#define NSTEPS 50
#define LATENT 128
#define HID 64
#define DTC 0.02f
#define SQRT_DT 0.14142135623730951f
#define LOG2E 1.4426950408889634f
#define LN2 0.6931471805599453f
#define EXPM50 1.9287498479639178e-22f /* exp(-50) */

typedef unsigned long long u64t;

// Scratch (no cudaMalloc allowed)
__device__ float g_zc[BB * HID];   // per-b hidden bias: z@W1[:,2:].T + b1
__device__ float g_halfb[BB];      // 0.5*boundary
__device__ float g_ndt[BB];        // non-decision time

__device__ __forceinline__ float ex2f(float v) {
    float r; asm("ex2.approx.f32 %0, %1;" : "=f"(r) : "f"(v)); return r;
}
__device__ __forceinline__ float lg2f(float v) {
    float r; asm("lg2.approx.f32 %0, %1;" : "=f"(r) : "f"(v)); return r;
}
__device__ __forceinline__ float tanhapx(float v) {
    float r; asm("tanh.approx.f32 %0, %1;" : "=f"(r) : "f"(v)); return r;
}
__device__ __forceinline__ u64t pack2(float lo, float hi) {
    u64t r;
    asm("mov.b64 %0, {%1, %2};" : "=l"(r)
        : "r"(__float_as_uint(lo)), "r"(__float_as_uint(hi)));
    return r;
}
__device__ __forceinline__ void unpack2(u64t v, float& lo, float& hi) {
    unsigned a, b;
    asm("mov.b64 {%0, %1}, %2;" : "=r"(a), "=r"(b) : "l"(v));
    lo = __uint_as_float(a); hi = __uint_as_float(b);
}
__device__ __forceinline__ u64t fma2(u64t a, u64t b, u64t c) {
    u64t r; asm("fma.rn.f32x2 %0, %1, %2, %3;" : "=l"(r) : "l"(a), "l"(b), "l"(c));
    return r;
}
__device__ __forceinline__ float fix_out(float v) {
    if (isnan(v)) return 0.0f;
    return fminf(fmaxf(v, -3.402823466e38f), 3.402823466e38f);
}

// ---------------------------------------------------------------------------
// Precompute: zc[b][j] = b1[j] + sum_k z[b,k]*W1[j,2+k]; boundary & ndt per b.
// ---------------------------------------------------------------------------
__global__ __launch_bounds__(256) void precompute_kernel(
    const float* __restrict__ z,  const float* __restrict__ W1,
    const float* __restrict__ b1, const float* __restrict__ Wb,
    const float* __restrict__ bbv, const float* __restrict__ Wn,
    const float* __restrict__ bnv)
{
    __shared__ __align__(16) float sW[HID * 130];   // whole W1, 33.3KB
    __shared__ __align__(16) float sz[16 * LATENT]; // 16 z rows, 8KB
    const int tid = threadIdx.x;
    const int b0 = blockIdx.x * 16;

    for (int i = tid; i < HID * 130; i += 256) sW[i] = W1[i];
    for (int i = tid; i < 16 * LATENT; i += 256) sz[i] = z[b0 * LATENT + i];
    __syncthreads();

    const int j = tid & 63;
    const int bg = tid >> 6;   // 0..3, each handles 4 b's
    const float* wrow = sW + j * 130 + 2;
    float a0, a1, a2, a3;
    a0 = a1 = a2 = a3 = b1[j];
    const float* z0 = sz + (bg * 4 + 0) * LATENT;
    const float* z1 = sz + (bg * 4 + 1) * LATENT;
    const float* z2 = sz + (bg * 4 + 2) * LATENT;
    const float* z3 = sz + (bg * 4 + 3) * LATENT;
    #pragma unroll 8
    for (int k = 0; k < LATENT; k += 4) {
        float w0 = wrow[k], w1 = wrow[k + 1], w2 = wrow[k + 2], w3 = wrow[k + 3];
        float4 q0 = *(const float4*)(z0 + k);
        float4 q1 = *(const float4*)(z1 + k);
        float4 q2 = *(const float4*)(z2 + k);
        float4 q3 = *(const float4*)(z3 + k);
        a0 = fmaf(w0, q0.x, a0); a0 = fmaf(w1, q0.y, a0); a0 = fmaf(w2, q0.z, a0); a0 = fmaf(w3, q0.w, a0);
        a1 = fmaf(w0, q1.x, a1); a1 = fmaf(w1, q1.y, a1); a1 = fmaf(w2, q1.z, a1); a1 = fmaf(w3, q1.w, a1);
        a2 = fmaf(w0, q2.x, a2); a2 = fmaf(w1, q2.y, a2); a2 = fmaf(w2, q2.z, a2); a2 = fmaf(w3, q2.w, a2);
        a3 = fmaf(w0, q3.x, a3); a3 = fmaf(w1, q3.y, a3); a3 = fmaf(w2, q3.z, a3); a3 = fmaf(w3, q3.w, a3);
    }
    g_zc[(b0 + bg * 4 + 0) * HID + j] = a0;
    g_zc[(b0 + bg * 4 + 1) * HID + j] = a1;
    g_zc[(b0 + bg * 4 + 2) * HID + j] = a2;
    g_zc[(b0 + bg * 4 + 3) * HID + j] = a3;

    if (tid < 32) {
        const int bl = tid >> 1;
        const int isn = tid & 1;
        const float* wv = isn ? Wn : Wb;
        const float* zz = sz + bl * LATENT;
        float acc = isn ? bnv[0] : bbv[0];
        #pragma unroll 8
        for (int k = 0; k < LATENT; k++) acc = fmaf(wv[k], zz[k], acc);
        float sp = fmaxf(acc, 0.0f) + log1pf(expf(-fabsf(acc)));
        if (isn) g_ndt[b0 + bl] = sp + 0.05f;
        else     g_halfb[b0 + bl] = 0.5f * (sp + 0.3f);
    }
}

// ---------------------------------------------------------------------------
// Main SDE kernel. One warp per b. Lane = (rep 0..3) x (sim-pair 0..7);
// each lane runs TWO independent sims (s, s+8) sharing the same weight regs.
// 16 hidden units per lane as 8 f32x2 pairs; tanh via MUFU.TANH.
// Block 128 = 4 b's.
// ---------------------------------------------------------------------------
__global__ __launch_bounds__(128, 3) void sde_kernel(
    const float* __restrict__ W1, const float* __restrict__ W2,
    const float* __restrict__ b2, const float* __restrict__ noise,
    const float* __restrict__ osc, const float* __restrict__ obi,
    float* __restrict__ out)
{
    const int tid = threadIdx.x;
    const int lane = tid & 31;
    const int rep = lane & 3;         // which 16-unit slice
    const int sp  = lane >> 2;        // sim pair: sims sp and sp+8
    const int bl  = tid >> 5;         // 0..3
    const int b   = blockIdx.x * 4 + bl;
    const int jbase = rep * 16;

    u64t w1x2[8], w1t2[8], zc2[8], w2a2[8], w2b2[8];
    #pragma unroll
    for (int p = 0; p < 8; p++) {
        const int j = jbase + p * 2;
        w1x2[p] = pack2(W1[j * 130],       W1[(j + 1) * 130]);
        w1t2[p] = pack2(W1[j * 130 + 1],   W1[(j + 1) * 130 + 1]);
        zc2[p]  = pack2(g_zc[b * HID + j], g_zc[b * HID + j + 1]);
        w2a2[p] = pack2(W2[j],             W2[j + 1]);
        w2b2[p] = pack2(W2[HID + j],       W2[HID + j + 1]);
    }
    const float b2x = b2[0], b2y = b2[1];
    const float half_b = g_halfb[b];

    float xA = 0.0f, pA = 1.0f, rtA = 0.0f, crA = 0.0f;
    float xB = 0.0f, pB = 1.0f, rtB = 0.0f, crB = 0.0f;
    const int nidxA = b * SS + sp;
    const int nidxB = nidxA + 8;
    float nzA = noise[nidxA];
    float nzB = noise[nidxB];

    #pragma unroll 1
    for (int k = 0; k < NSTEPS; k++) {
        const int k1 = (k + 1 < NSTEPS) ? (k + 1) : (NSTEPS - 1);
        const float nzA_n = noise[k1 * (BB * SS) + nidxA];
        const float nzB_n = noise[k1 * (BB * SS) + nidxB];
        const float tk = (float)k * DTC;
        const u64t tk2 = pack2(tk, tk);
        const u64t xA2 = pack2(xA, xA);
        const u64t xB2 = pack2(xB, xB);

        u64t daA = 0ull, dbA = 0ull, daB = 0ull, dbB = 0ull;
        #pragma unroll
        for (int p = 0; p < 8; p++) {
            const u64t base = fma2(tk2, w1t2[p], zc2[p]);   // shared A/B
            const u64t uA = fma2(xA2, w1x2[p], base);
            const u64t uB = fma2(xB2, w1x2[p], base);
            float al, ah, bl2, bh;
            unpack2(uA, al, ah);
            unpack2(uB, bl2, bh);
            const u64t hA = pack2(tanhapx(al), tanhapx(ah));
            const u64t hB = pack2(tanhapx(bl2), tanhapx(bh));
            daA = fma2(hA, w2a2[p], daA);
            dbA = fma2(hA, w2b2[p], dbA);
            daB = fma2(hB, w2a2[p], daB);
            dbB = fma2(hB, w2b2[p], dbB);
        }
        float t0, t1;
        unpack2(daA, t0, t1); float pdA = t0 + t1;
        unpack2(dbA, t0, t1); float pfA = t0 + t1;
        unpack2(daB, t0, t1); float pdB = t0 + t1;
        unpack2(dbB, t0, t1); float pfB = t0 + t1;
        pdA += __shfl_xor_sync(0xffffffffu, pdA, 1);
        pfA += __shfl_xor_sync(0xffffffffu, pfA, 1);
        pdB += __shfl_xor_sync(0xffffffffu, pdB, 1);
        pfB += __shfl_xor_sync(0xffffffffu, pfB, 1);
        pdA += __shfl_xor_sync(0xffffffffu, pdA, 2);
        pfA += __shfl_xor_sync(0xffffffffu, pfA, 2);
        pdB += __shfl_xor_sync(0xffffffffu, pdB, 2);
        pfB += __shfl_xor_sync(0xffffffffu, pfB, 2);

        // --- tail, sim A ---
        {
            const float dyn0 = pdA + b2x;
            const float dyn1 = pfA + b2y;
            const float drift = fminf(fmaxf(dyn0, -5.0f), 5.0f);
            const float e1 = ex2f(-fabsf(dyn1) * LOG2E);
            const float spv = fmaxf(dyn1, 0.0f) + lg2f(1.0f + e1) * LN2;
            const float diff = spv + 0.1f;
            xA = fmaf(diff * SQRT_DT, nzA, fmaf(drift, DTC, xA));
            xA = fminf(fmaxf(xA, -10.0f), 10.0f);
            const float dist = fabsf(xA) - half_b;
            const float sg = fmaf(0.5f, tanhapx(10.0f * dist), 0.5f);
            const float hz = fminf(fmaxf(sg, 0.0f), 0.99f);
            const float sb = fmaxf(pA, EXPM50);
            const float cp = sb * hz;
            pA = pA * (1.0f - hz);
            rtA = fmaf(cp, tk + DTC, rtA);
            crA += (xA > 0.0f) ? cp : 0.0f;
        }
        // --- tail, sim B ---
        {
            const float dyn0 = pdB + b2x;
            const float dyn1 = pfB + b2y;
            const float drift = fminf(fmaxf(dyn0, -5.0f), 5.0f);
            const float e1 = ex2f(-fabsf(dyn1) * LOG2E);
            const float spv = fmaxf(dyn1, 0.0f) + lg2f(1.0f + e1) * LN2;
            const float diff = spv + 0.1f;
            xB = fmaf(diff * SQRT_DT, nzB, fmaf(drift, DTC, xB));
            xB = fminf(fmaxf(xB, -10.0f), 10.0f);
            const float dist = fabsf(xB) - half_b;
            const float sg = fmaf(0.5f, tanhapx(10.0f * dist), 0.5f);
            const float hz = fminf(fmaxf(sg, 0.0f), 0.99f);
            const float sb = fmaxf(pB, EXPM50);
            const float cp = sb * hz;
            pB = pB * (1.0f - hz);
            rtB = fmaf(cp, tk + DTC, rtB);
            crB += (xB > 0.0f) ? cp : 0.0f;
        }

        nzA = nzA_n;
        nzB = nzB_n;
    }

    const float remA = fmaxf(pA, EXPM50);
    const float remB = fmaxf(pB, EXPM50);
    rtA = fmaf(remA, (float)NSTEPS * DTC, rtA);
    rtB = fmaf(remB, (float)NSTEPS * DTC, rtB);
    crA = fmaf(remA, 0.5f, crA);
    crB = fmaf(remB, 0.5f, crB);
    const float ndt = g_ndt[b];
    const float rtmsA = (rtA + ndt) * 1000.0f;
    const float rtmsB = (rtB + ndt) * 1000.0f;

    // per-b reduction over the 16 sims
    __shared__ float s_rt[4][16];
    __shared__ float s_cr[4][16];
    if (rep == 0) {
        s_rt[bl][sp]     = rtmsA;  s_cr[bl][sp]     = crA;
        s_rt[bl][sp + 8] = rtmsB;  s_cr[bl][sp + 8] = crB;
    }
    __syncthreads();

    if (tid < 4) {
        float m = 0.0f, c = 0.0f;
        #pragma unroll
        for (int i = 0; i < 16; i++) { m += s_rt[tid][i]; c += s_cr[tid][i]; }
        m *= (1.0f / 16.0f);
        c *= (1.0f / 16.0f);
        float v = 0.0f;
        #pragma unroll
        for (int i = 0; i < 16; i++) {
            float d = s_rt[tid][i] - m;
            v = fmaf(d, d, v);
        }
        const float sd = sqrtf(v * (1.0f / 15.0f));  // ddof=1
        const int bo = blockIdx.x * 4 + tid;
        const float o0 = m * osc[0] + obi[0];
        const float o1 = (sd + 0.001f) * osc[1] + obi[1];
        const float o2 = c * osc[2] + obi[2];
        out[bo * 3 + 0] = fix_out(o0);
        out[bo * 3 + 1] = fix_out(o1);
        out[bo * 3 + 2] = fix_out(o2);
    }
}

extern "C" void kernel_launch(void* const* d_in, const int* in_sizes, int n_in,
                              void* d_out, int out_size)
{
    const float* z   = (const float*)d_in[0];
    const float* W1  = (const float*)d_in[1];
    const float* b1  = (const float*)d_in[2];
    const float* W2  = (const float*)d_in[3];
    const float* b2  = (const float*)d_in[4];
    const float* Wb  = (const float*)d_in[5];
    const float* bbv = (const float*)d_in[6];
    const float* Wn  = (const float*)d_in[7];
    const float* bnv = (const float*)d_in[8];
    const float* osc = (const float*)d_in[9];
    const float* obi = (const float*)d_in[10];
    const float* noise = (const float*)d_in[11];
    float* out = (float*)d_out;

    precompute_kernel<<<BB / 16, 256>>>(z, W1, b1, Wb, bbv, Wn, bnv);
    sde_kernel<<<BB / 4, 128>>>(W1, W2, b2, noise, osc, obi, out);
}